// round 1
// baseline (speedup 1.0000x reference)
#include <cuda_runtime.h>

#define BB 4
#define LL 4096
#define HH 16
#define DD 128
#define BH (BB*HH)            // 64
#define SPLITS 8
#define LSPLIT (LL/SPLITS)    // 512
#define STRIDE_L (HH*DD)      // 2048 floats between consecutive l for fixed (b,h)
#define PAD 132               // row padding: 132 floats = 528B = 33*16B (keeps float4 alignment)
#define EPS 1e-6f

// ---------------- scratch (device globals; no allocation allowed) ----------------
__device__ float g_qpart[BH*SPLITS*DD];
__device__ float g_qglob[BH*DD];
__device__ float g_alpha[BH*LL];                 // scores, then overwritten with alpha
__device__ float g_kvpart[(size_t)BH*SPLITS*DD*DD];  // 33.5 MB split-K partials
__device__ float g_ksumpart[BH*SPLITS*DD];
__device__ float g_kv[BH*DD*DD];                 // 4 MB
__device__ float g_ksum[BH*DD];

__device__ __forceinline__ size_t head_base(int bh) {
    // offset (in floats) of element (b, l=0, h, d=0)
    return (size_t)(bh >> 4) * LL * STRIDE_L + (size_t)(bh & 15) * DD;
}

// ---------------- K1: partial sums of Q over L ----------------
// grid (SPLITS, BH), block 128 (one thread per d)
__global__ void k_qsum(const float* __restrict__ Q) {
    int split = blockIdx.x, bh = blockIdx.y, d = threadIdx.x;
    const float* p = Q + head_base(bh) + (size_t)split * LSPLIT * STRIDE_L + d;
    float acc = 0.f;
#pragma unroll 8
    for (int l = 0; l < LSPLIT; l++) acc += p[(size_t)l * STRIDE_L];
    g_qpart[(bh * SPLITS + split) * DD + d] = acc;
}

// ---------------- K2: reduce partials -> q_global ----------------
// grid BH, block 128
__global__ void k_qred() {
    int bh = blockIdx.x, d = threadIdx.x;
    float acc = 0.f;
#pragma unroll
    for (int s = 0; s < SPLITS; s++) acc += g_qpart[(bh * SPLITS + s) * DD + d];
    // mean over L, then / sqrt(EMBED_DIM=2048)
    g_qglob[bh * DD + d] = acc * (1.0f / (float)LL) * rsqrtf(2048.0f);
}

// ---------------- K3: scores[bh][l] = q_global . K[l] ----------------
// grid (BH, LL/8), block 256 (8 warps, one l per warp)
__global__ void k_scores(const float* __restrict__ K) {
    __shared__ float4 qg[32];
    int bh = blockIdx.x;
    int tid = threadIdx.x;
    if (tid < 32) qg[tid] = ((const float4*)(g_qglob + bh * DD))[tid];
    __syncthreads();
    int w = tid >> 5, lane = tid & 31;
    int l = blockIdx.y * 8 + w;
    const float4* kp = (const float4*)(K + head_base(bh) + (size_t)l * STRIDE_L);
    float4 kv = kp[lane];
    float4 q  = qg[lane];
    float s = kv.x * q.x + kv.y * q.y + kv.z * q.z + kv.w * q.w;
#pragma unroll
    for (int o = 16; o; o >>= 1) s += __shfl_xor_sync(0xffffffffu, s, o);
    if (lane == 0) g_alpha[bh * LL + l] = s;
}

// ---------------- K4: softmax over L, in-place alpha = exp(s-m)/sum * L ----------------
// grid BH, block 256
__global__ void k_softmax() {
    __shared__ float red[256];
    int bh = blockIdx.x, tid = threadIdx.x;
    float* s = g_alpha + bh * LL;
    float m = -1e30f;
    for (int i = tid; i < LL; i += 256) m = fmaxf(m, s[i]);
    red[tid] = m; __syncthreads();
    for (int o = 128; o; o >>= 1) { if (tid < o) red[tid] = fmaxf(red[tid], red[tid + o]); __syncthreads(); }
    m = red[0]; __syncthreads();
    float sum = 0.f;
    for (int i = tid; i < LL; i += 256) sum += expf(s[i] - m);
    red[tid] = sum; __syncthreads();
    for (int o = 128; o; o >>= 1) { if (tid < o) red[tid] += red[tid + o]; __syncthreads(); }
    float scale = (float)LL / red[0];
    for (int i = tid; i < LL; i += 256) s[i] = expf(s[i] - m) * scale;
}

// ---------------- K5: split-K GEMM  KVpart[d][e] = sum_l (alpha[l]*phiK[l][d]) * V[l][e] ----------------
// grid (SPLITS, BH), block 256, 2 blocks/SM
__global__ void __launch_bounds__(256, 2) k_kv(const float* __restrict__ phiK,
                                               const float* __restrict__ V) {
    __shared__ float As[32][PAD];      // alpha-scaled phiK tile [l][d]
    __shared__ float Bs[32][PAD];      // V tile [l][e]
    __shared__ float ks_red[8][DD];    // ksum cross-thread reduce

    int split = blockIdx.x, bh = blockIdx.y, tid = threadIdx.x;
    size_t base = head_base(bh);
    int l0 = split * LSPLIT;
    int tx = tid & 15, ty = tid >> 4;
    int ld_d4 = tid & 31;   // float4 column index (d/4 or e/4)
    int ld_r  = tid >> 5;   // 0..7 row-in-tile group

    const float* alpha = g_alpha + bh * LL + l0;

    float acc[8][8];
#pragma unroll
    for (int i = 0; i < 8; i++)
#pragma unroll
        for (int j = 0; j < 8; j++) acc[i][j] = 0.f;
    float ks0 = 0.f, ks1 = 0.f, ks2 = 0.f, ks3 = 0.f;

    for (int t = 0; t < LSPLIT; t += 32) {
        __syncthreads();
#pragma unroll
        for (int j = 0; j < 4; j++) {
            int lr = ld_r + 8 * j;              // row in tile
            int l  = t + lr;                     // row in split
            float a = alpha[l];
            const float* gp = phiK + base + (size_t)(l0 + l) * STRIDE_L + ld_d4 * 4;
            const float* gv = V    + base + (size_t)(l0 + l) * STRIDE_L + ld_d4 * 4;
            float4 pk = *(const float4*)gp;
            pk.x *= a; pk.y *= a; pk.z *= a; pk.w *= a;
            ((float4*)&As[lr][0])[ld_d4] = pk;
            ks0 += pk.x; ks1 += pk.y; ks2 += pk.z; ks3 += pk.w;
            ((float4*)&Bs[lr][0])[ld_d4] = *(const float4*)gv;
        }
        __syncthreads();
#pragma unroll 8
        for (int k = 0; k < 32; k++) {
            float4 a0 = *(const float4*)&As[k][ty * 8];
            float4 a1 = *(const float4*)&As[k][ty * 8 + 4];
            float4 b0 = *(const float4*)&Bs[k][tx * 4];
            float4 b1 = *(const float4*)&Bs[k][tx * 4 + 64];
            float av[8] = {a0.x, a0.y, a0.z, a0.w, a1.x, a1.y, a1.z, a1.w};
            float bv[8] = {b0.x, b0.y, b0.z, b0.w, b1.x, b1.y, b1.z, b1.w};
#pragma unroll
            for (int i = 0; i < 8; i++)
#pragma unroll
                for (int j = 0; j < 8; j++) acc[i][j] += av[i] * bv[j];
        }
    }

    // write KV partials: rows ty*8+i (d), cols tx*4+j and 64+tx*4+j (e)
    float* dstbase = g_kvpart + ((size_t)(bh * SPLITS + split) * DD) * DD;
#pragma unroll
    for (int i = 0; i < 8; i++) {
        float* dst = dstbase + (size_t)(ty * 8 + i) * DD;
        float4 o0 = make_float4(acc[i][0], acc[i][1], acc[i][2], acc[i][3]);
        float4 o1 = make_float4(acc[i][4], acc[i][5], acc[i][6], acc[i][7]);
        *(float4*)(dst + tx * 4)      = o0;
        *(float4*)(dst + 64 + tx * 4) = o1;
    }

    // ksum partial reduce across the 8 row-groups
    ((float4*)&ks_red[ld_r][0])[ld_d4] = make_float4(ks0, ks1, ks2, ks3);
    __syncthreads();
    if (tid < 32) {
        float4 s = make_float4(0.f, 0.f, 0.f, 0.f);
#pragma unroll
        for (int r = 0; r < 8; r++) {
            float4 v = ((float4*)&ks_red[r][0])[tid];
            s.x += v.x; s.y += v.y; s.z += v.z; s.w += v.w;
        }
        *(float4*)(g_ksumpart + (bh * SPLITS + split) * DD + tid * 4) = s;
    }
}

// ---------------- K6: reduce split-K partials ----------------
// grid (16, BH), block 1024
__global__ void k_kvred() {
    int bh = blockIdx.y;
    int idx = blockIdx.x * 1024 + threadIdx.x;   // 0..16383
    float acc = 0.f;
#pragma unroll
    for (int s = 0; s < SPLITS; s++)
        acc += g_kvpart[((size_t)(bh * SPLITS + s) * DD) * DD + idx];
    g_kv[(size_t)bh * DD * DD + idx] = acc;
    if (blockIdx.x == 0 && threadIdx.x < DD) {
        float a = 0.f;
#pragma unroll
        for (int s = 0; s < SPLITS; s++) a += g_ksumpart[(bh * SPLITS + s) * DD + threadIdx.x];
        g_ksum[bh * DD + threadIdx.x] = a;
    }
}

// ---------------- K7: out[l][e] = (phiQ[l][:] @ KV[:,e]) / (phiQ[l][:].ksum + eps) ----------------
// grid (LL/128, BH), block 256, dynamic smem = 2*128*PAD*4 = 132 KB
__global__ void __launch_bounds__(256, 1) k_out(const float* __restrict__ phiQ,
                                                float* __restrict__ out) {
    extern __shared__ float sm[];
    float* KVs = sm;               // [128][PAD]  (d-major)
    float* Qs  = sm + DD * PAD;    // [128][PAD]  (l-major)
    __shared__ float den[DD];
    __shared__ float ks[DD];

    int chunk = blockIdx.x, bh = blockIdx.y, tid = threadIdx.x;
    size_t base = head_base(bh);
    int l0 = chunk * 128;

    // load KV tile (L2-resident across the 32 chunks of this head)
    const float4* kvsrc = (const float4*)(g_kv + (size_t)bh * DD * DD);
    for (int i = tid; i < DD * DD / 4; i += 256) {
        int r = i >> 5, c4 = i & 31;
        ((float4*)(KVs + r * PAD))[c4] = kvsrc[i];
    }
    if (tid < DD) ks[tid] = g_ksum[bh * DD + tid];
    // load phiQ tile rows l0..l0+127
    for (int i = tid; i < 128 * 32; i += 256) {
        int r = i >> 5, c4 = i & 31;
        ((float4*)(Qs + r * PAD))[c4] =
            *(const float4*)(phiQ + base + (size_t)(l0 + r) * STRIDE_L + c4 * 4);
    }
    __syncthreads();

    // denominator: warp w handles rows w*16..w*16+15
    {
        int w = tid >> 5, lane = tid & 31;
        for (int r = w * 16; r < w * 16 + 16; r++) {
            float4 q = ((const float4*)(Qs + r * PAD))[lane];
            float4 k4 = ((const float4*)ks)[lane];
            float d = q.x * k4.x + q.y * k4.y + q.z * k4.z + q.w * k4.w;
#pragma unroll
            for (int o = 16; o; o >>= 1) d += __shfl_xor_sync(0xffffffffu, d, o);
            if (lane == 0) den[r] = d + EPS;
        }
    }
    __syncthreads();

    int tx = tid & 15, ty = tid >> 4;
    float acc[8][8];
#pragma unroll
    for (int i = 0; i < 8; i++)
#pragma unroll
        for (int j = 0; j < 8; j++) acc[i][j] = 0.f;

#pragma unroll 4
    for (int k = 0; k < DD; k++) {
        float av[8];
#pragma unroll
        for (int i = 0; i < 8; i++) av[i] = Qs[(ty * 8 + i) * PAD + k];
        float4 b0 = ((const float4*)(KVs + k * PAD))[tx];        // cols tx*4..+3
        float4 b1 = ((const float4*)(KVs + k * PAD))[16 + tx];   // cols 64+tx*4..+3
        float bv[8] = {b0.x, b0.y, b0.z, b0.w, b1.x, b1.y, b1.z, b1.w};
#pragma unroll
        for (int i = 0; i < 8; i++)
#pragma unroll
            for (int j = 0; j < 8; j++) acc[i][j] += av[i] * bv[j];
    }

#pragma unroll
    for (int i = 0; i < 8; i++) {
        int l = ty * 8 + i;
        float dinv = 1.0f / den[l];
        float* dst = out + base + (size_t)(l0 + l) * STRIDE_L;
        float4 o0 = make_float4(acc[i][0] * dinv, acc[i][1] * dinv, acc[i][2] * dinv, acc[i][3] * dinv);
        float4 o1 = make_float4(acc[i][4] * dinv, acc[i][5] * dinv, acc[i][6] * dinv, acc[i][7] * dinv);
        *(float4*)(dst + tx * 4)      = o0;
        *(float4*)(dst + 64 + tx * 4) = o1;
    }
}

// ---------------- launch ----------------
extern "C" void kernel_launch(void* const* d_in, const int* in_sizes, int n_in,
                              void* d_out, int out_size) {
    const float* Q    = (const float*)d_in[0];
    const float* K    = (const float*)d_in[1];
    const float* V    = (const float*)d_in[2];
    const float* phiQ = (const float*)d_in[3];
    const float* phiK = (const float*)d_in[4];
    float* out = (float*)d_out;

    static bool attr_set = false;
    if (!attr_set) {
        cudaFuncSetAttribute(k_out, cudaFuncAttributeMaxDynamicSharedMemorySize,
                             2 * DD * PAD * (int)sizeof(float));
        attr_set = true;
    }

    k_qsum<<<dim3(SPLITS, BH), 128>>>(Q);
    k_qred<<<BH, 128>>>();
    k_scores<<<dim3(BH, LL / 8), 256>>>(K);
    k_softmax<<<BH, 256>>>();
    k_kv<<<dim3(SPLITS, BH), 256>>>(phiK, V);
    k_kvred<<<dim3(16, BH), 1024>>>();
    k_out<<<dim3(LL / 128, BH), 256, 2 * DD * PAD * (int)sizeof(float)>>>(phiQ, out);
}

// round 2
// speedup vs baseline: 1.0267x; 1.0267x over previous
#include <cuda_runtime.h>

#define BB 4
#define LL 4096
#define HH 16
#define DD 128
#define BH (BB*HH)            // 64
#define SPLITS 8
#define LSPLIT (LL/SPLITS)    // 512
#define STRIDE_L (HH*DD)      // 2048 floats between consecutive l for fixed (b,h)
#define PAD 132               // row padding: 132 floats = 528B = 33*16B (keeps float4 alignment)
#define EPS 1e-6f

// ---------------- scratch (device globals; no allocation allowed) ----------------
__device__ float g_qpart[BH*SPLITS*DD];
__device__ float g_qglob[BH*DD];
__device__ float g_alpha[BH*LL];                 // scores, then overwritten with alpha
__device__ float g_kvpart[(size_t)BH*SPLITS*DD*DD];  // 33.5 MB split-K partials
__device__ float g_ksumpart[BH*SPLITS*DD];
__device__ float g_kv[BH*DD*DD];                 // 4 MB
__device__ float g_ksum[BH*DD];

__device__ __forceinline__ size_t head_base(int bh) {
    return (size_t)(bh >> 4) * LL * STRIDE_L + (size_t)(bh & 15) * DD;
}

// ---------------- packed f32x2 helpers (FFMA2 path, sm_100+) ----------------
__device__ __forceinline__ unsigned long long pack2(float v) {
    unsigned long long r;
    asm("mov.b64 %0, {%1, %1};" : "=l"(r) : "f"(v));
    return r;
}
__device__ __forceinline__ void ffma2(unsigned long long& d,
                                      unsigned long long a,
                                      unsigned long long b) {
    asm("fma.rn.f32x2 %0, %1, %2, %0;" : "+l"(d) : "l"(a), "l"(b));
}
__device__ __forceinline__ unsigned long long mul2(unsigned long long a,
                                                   unsigned long long b) {
    unsigned long long r;
    asm("mul.rn.f32x2 %0, %1, %2;" : "=l"(r) : "l"(a), "l"(b));
    return r;
}

// ---------------- K1: partial sums of Q over L ----------------
__global__ void k_qsum(const float* __restrict__ Q) {
    int split = blockIdx.x, bh = blockIdx.y, d = threadIdx.x;
    const float* p = Q + head_base(bh) + (size_t)split * LSPLIT * STRIDE_L + d;
    float acc = 0.f;
#pragma unroll 8
    for (int l = 0; l < LSPLIT; l++) acc += p[(size_t)l * STRIDE_L];
    g_qpart[(bh * SPLITS + split) * DD + d] = acc;
}

// ---------------- K2: reduce partials -> q_global ----------------
__global__ void k_qred() {
    int bh = blockIdx.x, d = threadIdx.x;
    float acc = 0.f;
#pragma unroll
    for (int s = 0; s < SPLITS; s++) acc += g_qpart[(bh * SPLITS + s) * DD + d];
    g_qglob[bh * DD + d] = acc * (1.0f / (float)LL) * rsqrtf(2048.0f);
}

// ---------------- K3: scores[bh][l] = q_global . K[l] ----------------
__global__ void k_scores(const float* __restrict__ K) {
    __shared__ float4 qg[32];
    int bh = blockIdx.x;
    int tid = threadIdx.x;
    if (tid < 32) qg[tid] = ((const float4*)(g_qglob + bh * DD))[tid];
    __syncthreads();
    int w = tid >> 5, lane = tid & 31;
    int l = blockIdx.y * 8 + w;
    const float4* kp = (const float4*)(K + head_base(bh) + (size_t)l * STRIDE_L);
    float4 kv = kp[lane];
    float4 q  = qg[lane];
    float s = kv.x * q.x + kv.y * q.y + kv.z * q.z + kv.w * q.w;
#pragma unroll
    for (int o = 16; o; o >>= 1) s += __shfl_xor_sync(0xffffffffu, s, o);
    if (lane == 0) g_alpha[bh * LL + l] = s;
}

// ---------------- K4: softmax over L, in-place alpha = exp(s-m)/sum * L ----------------
__global__ void k_softmax() {
    __shared__ float red[256];
    int bh = blockIdx.x, tid = threadIdx.x;
    float* s = g_alpha + bh * LL;
    float m = -1e30f;
    for (int i = tid; i < LL; i += 256) m = fmaxf(m, s[i]);
    red[tid] = m; __syncthreads();
    for (int o = 128; o; o >>= 1) { if (tid < o) red[tid] = fmaxf(red[tid], red[tid + o]); __syncthreads(); }
    m = red[0]; __syncthreads();
    float sum = 0.f;
    for (int i = tid; i < LL; i += 256) {
        float e = expf(s[i] - m);
        s[i] = e;                 // store exp once; rescale in last pass
        sum += e;
    }
    red[tid] = sum; __syncthreads();
    for (int o = 128; o; o >>= 1) { if (tid < o) red[tid] += red[tid + o]; __syncthreads(); }
    float scale = (float)LL / red[0];
    for (int i = tid; i < LL; i += 256) s[i] *= scale;
}

// ---------------- K5: split-K GEMM  KVpart[d][e] = sum_l (alpha[l]*phiK[l][d]) * V[l][e] ----------------
__global__ void __launch_bounds__(256, 2) k_kv(const float* __restrict__ phiK,
                                               const float* __restrict__ V) {
    __shared__ __align__(16) float As[32][PAD];   // alpha-scaled phiK tile [l][d]
    __shared__ __align__(16) float Bs[32][PAD];   // V tile [l][e]
    __shared__ float ks_red[8][DD];

    int split = blockIdx.x, bh = blockIdx.y, tid = threadIdx.x;
    size_t base = head_base(bh);
    int l0 = split * LSPLIT;
    int tx = tid & 15, ty = tid >> 4;
    int ld_d4 = tid & 31;
    int ld_r  = tid >> 5;

    const float* alpha = g_alpha + bh * LL + l0;

    unsigned long long acc2[8][4];                // [i][j2]: cols (tx*4 + 2*j2 ..) packed pairs
#pragma unroll
    for (int i = 0; i < 8; i++)
#pragma unroll
        for (int j = 0; j < 4; j++) acc2[i][j] = 0ULL;
    float ks0 = 0.f, ks1 = 0.f, ks2 = 0.f, ks3 = 0.f;

    for (int t = 0; t < LSPLIT; t += 32) {
        __syncthreads();
#pragma unroll
        for (int j = 0; j < 4; j++) {
            int lr = ld_r + 8 * j;
            int l  = t + lr;
            float a = alpha[l];
            const float* gp = phiK + base + (size_t)(l0 + l) * STRIDE_L + ld_d4 * 4;
            const float* gv = V    + base + (size_t)(l0 + l) * STRIDE_L + ld_d4 * 4;
            float4 pk = *(const float4*)gp;
            pk.x *= a; pk.y *= a; pk.z *= a; pk.w *= a;
            ((float4*)&As[lr][0])[ld_d4] = pk;
            ks0 += pk.x; ks1 += pk.y; ks2 += pk.z; ks3 += pk.w;
            ((float4*)&Bs[lr][0])[ld_d4] = *(const float4*)gv;
        }
        __syncthreads();
#pragma unroll 8
        for (int k = 0; k < 32; k++) {
            float4 a0 = *(const float4*)&As[k][ty * 8];
            float4 a1 = *(const float4*)&As[k][ty * 8 + 4];
            ulonglong2 b0 = *(const ulonglong2*)&Bs[k][tx * 4];
            ulonglong2 b1 = *(const ulonglong2*)&Bs[k][tx * 4 + 64];
            unsigned long long bv[4] = {b0.x, b0.y, b1.x, b1.y};
            float av[8] = {a0.x, a0.y, a0.z, a0.w, a1.x, a1.y, a1.z, a1.w};
#pragma unroll
            for (int i = 0; i < 8; i++) {
                unsigned long long ad = pack2(av[i]);
#pragma unroll
                for (int j = 0; j < 4; j++) ffma2(acc2[i][j], ad, bv[j]);
            }
        }
    }

    // write KV partials: rows ty*8+i (d), packed cols
    float* dstbase = g_kvpart + ((size_t)(bh * SPLITS + split) * DD) * DD;
#pragma unroll
    for (int i = 0; i < 8; i++) {
        float* dst = dstbase + (size_t)(ty * 8 + i) * DD;
        ulonglong2 o0, o1;
        o0.x = acc2[i][0]; o0.y = acc2[i][1];
        o1.x = acc2[i][2]; o1.y = acc2[i][3];
        *(ulonglong2*)(dst + tx * 4)      = o0;
        *(ulonglong2*)(dst + 64 + tx * 4) = o1;
    }

    ((float4*)&ks_red[ld_r][0])[ld_d4] = make_float4(ks0, ks1, ks2, ks3);
    __syncthreads();
    if (tid < 32) {
        float4 s = make_float4(0.f, 0.f, 0.f, 0.f);
#pragma unroll
        for (int r = 0; r < 8; r++) {
            float4 v = ((float4*)&ks_red[r][0])[tid];
            s.x += v.x; s.y += v.y; s.z += v.z; s.w += v.w;
        }
        *(float4*)(g_ksumpart + (bh * SPLITS + split) * DD + tid * 4) = s;
    }
}

// ---------------- K6: reduce split-K partials ----------------
__global__ void k_kvred() {
    int bh = blockIdx.y;
    int idx = blockIdx.x * 1024 + threadIdx.x;
    float acc = 0.f;
#pragma unroll
    for (int s = 0; s < SPLITS; s++)
        acc += g_kvpart[((size_t)(bh * SPLITS + s) * DD) * DD + idx];
    g_kv[(size_t)bh * DD * DD + idx] = acc;
    if (blockIdx.x == 0 && threadIdx.x < DD) {
        float a = 0.f;
#pragma unroll
        for (int s = 0; s < SPLITS; s++) a += g_ksumpart[(bh * SPLITS + s) * DD + threadIdx.x];
        g_ksum[bh * DD + threadIdx.x] = a;
    }
}

// ---------------- K7: out[l][e] = (phiQ[l][:] @ KV[:,e]) / (phiQ[l][:].ksum + eps) ----------------
__global__ void __launch_bounds__(256, 1) k_out(const float* __restrict__ phiQ,
                                                float* __restrict__ out) {
    extern __shared__ __align__(16) float sm[];
    float* KVs = sm;               // [128][PAD]
    float* Qs  = sm + DD * PAD;    // [128][PAD]
    __shared__ float den[DD];
    __shared__ float ks[DD];

    int chunk = blockIdx.x, bh = blockIdx.y, tid = threadIdx.x;
    size_t base = head_base(bh);
    int l0 = chunk * 128;

    const float4* kvsrc = (const float4*)(g_kv + (size_t)bh * DD * DD);
    for (int i = tid; i < DD * DD / 4; i += 256) {
        int r = i >> 5, c4 = i & 31;
        ((float4*)(KVs + r * PAD))[c4] = kvsrc[i];
    }
    if (tid < DD) ks[tid] = g_ksum[bh * DD + tid];
    for (int i = tid; i < 128 * 32; i += 256) {
        int r = i >> 5, c4 = i & 31;
        ((float4*)(Qs + r * PAD))[c4] =
            *(const float4*)(phiQ + base + (size_t)(l0 + r) * STRIDE_L + c4 * 4);
    }
    __syncthreads();

    {
        int w = tid >> 5, lane = tid & 31;
        for (int r = w * 16; r < w * 16 + 16; r++) {
            float4 q = ((const float4*)(Qs + r * PAD))[lane];
            float4 k4 = ((const float4*)ks)[lane];
            float d = q.x * k4.x + q.y * k4.y + q.z * k4.z + q.w * k4.w;
#pragma unroll
            for (int o = 16; o; o >>= 1) d += __shfl_xor_sync(0xffffffffu, d, o);
            if (lane == 0) den[r] = d + EPS;
        }
    }
    __syncthreads();

    int tx = tid & 15, ty = tid >> 4;
    unsigned long long acc2[8][4];
#pragma unroll
    for (int i = 0; i < 8; i++)
#pragma unroll
        for (int j = 0; j < 4; j++) acc2[i][j] = 0ULL;

#pragma unroll 8
    for (int k = 0; k < DD; k++) {
        float av[8];
#pragma unroll
        for (int i = 0; i < 8; i++) av[i] = Qs[(ty * 8 + i) * PAD + k];
        ulonglong2 b0 = *(const ulonglong2*)(KVs + k * PAD + tx * 4);
        ulonglong2 b1 = *(const ulonglong2*)(KVs + k * PAD + 64 + tx * 4);
        unsigned long long bv[4] = {b0.x, b0.y, b1.x, b1.y};
#pragma unroll
        for (int i = 0; i < 8; i++) {
            unsigned long long ad = pack2(av[i]);
#pragma unroll
            for (int j = 0; j < 4; j++) ffma2(acc2[i][j], ad, bv[j]);
        }
    }

#pragma unroll
    for (int i = 0; i < 8; i++) {
        int l = ty * 8 + i;
        unsigned long long dinv2 = pack2(1.0f / den[l]);
        float* dst = out + base + (size_t)(l0 + l) * STRIDE_L;
        ulonglong2 o0, o1;
        o0.x = mul2(acc2[i][0], dinv2); o0.y = mul2(acc2[i][1], dinv2);
        o1.x = mul2(acc2[i][2], dinv2); o1.y = mul2(acc2[i][3], dinv2);
        *(ulonglong2*)(dst + tx * 4)      = o0;
        *(ulonglong2*)(dst + 64 + tx * 4) = o1;
    }
}

// ---------------- launch ----------------
extern "C" void kernel_launch(void* const* d_in, const int* in_sizes, int n_in,
                              void* d_out, int out_size) {
    const float* Q    = (const float*)d_in[0];
    const float* K    = (const float*)d_in[1];
    const float* V    = (const float*)d_in[2];
    const float* phiQ = (const float*)d_in[3];
    const float* phiK = (const float*)d_in[4];
    float* out = (float*)d_out;

    static bool attr_set = false;
    if (!attr_set) {
        cudaFuncSetAttribute(k_out, cudaFuncAttributeMaxDynamicSharedMemorySize,
                             2 * DD * PAD * (int)sizeof(float));
        attr_set = true;
    }

    k_qsum<<<dim3(SPLITS, BH), 128>>>(Q);
    k_qred<<<BH, 128>>>();
    k_scores<<<dim3(BH, LL / 8), 256>>>(K);
    k_softmax<<<BH, 256>>>();
    k_kv<<<dim3(SPLITS, BH), 256>>>(phiK, V);
    k_kvred<<<dim3(16, BH), 1024>>>();
    k_out<<<dim3(LL / 128, BH), 256, 2 * DD * PAD * (int)sizeof(float)>>>(phiQ, out);
}

// round 4
// speedup vs baseline: 1.0278x; 1.0011x over previous
#include <cuda_runtime.h>

#define BB 4
#define LL 4096
#define HH 16
#define DD 128
#define BH (BB*HH)            // 64
#define SPLITS 8
#define LSPLIT (LL/SPLITS)    // 512
#define STRIDE_L (HH*DD)      // 2048 floats between consecutive l for fixed (b,h)
#define PAD 132               // row padding: 132 floats = 528B = 33*16B (keeps float4 alignment)
#define EPS 1e-6f

// ---------------- scratch (device globals; no allocation allowed) ----------------
__device__ float g_qpart[BH*SPLITS*DD];
__device__ float g_qglob[BH*DD];
__device__ float g_alpha[BH*LL];                 // scores, then overwritten with alpha
__device__ float g_kvpart[(size_t)BH*SPLITS*DD*DD];  // 33.5 MB split-K partials
__device__ float g_ksumpart[BH*SPLITS*DD];
__device__ float g_kv[BH*DD*DD];                 // 4 MB
__device__ float g_ksum[BH*DD];

__device__ __forceinline__ size_t head_base(int bh) {
    return (size_t)(bh >> 4) * LL * STRIDE_L + (size_t)(bh & 15) * DD;
}

// ---------------- packed f32x2 helpers (FFMA2 path, sm_100+) ----------------
__device__ __forceinline__ unsigned long long pack2(float v) {
    unsigned long long r;
    asm("mov.b64 %0, {%1, %1};" : "=l"(r) : "f"(v));
    return r;
}
__device__ __forceinline__ void ffma2(unsigned long long& d,
                                      unsigned long long a,
                                      unsigned long long b) {
    asm("fma.rn.f32x2 %0, %1, %2, %0;" : "+l"(d) : "l"(a), "l"(b));
}
__device__ __forceinline__ unsigned long long mul2(unsigned long long a,
                                                   unsigned long long b) {
    unsigned long long r;
    asm("mul.rn.f32x2 %0, %1, %2;" : "=l"(r) : "l"(a), "l"(b));
    return r;
}

// ---------------- K1: partial sums of Q over L ----------------
__global__ void k_qsum(const float* __restrict__ Q) {
    int split = blockIdx.x, bh = blockIdx.y, d = threadIdx.x;
    const float* p = Q + head_base(bh) + (size_t)split * LSPLIT * STRIDE_L + d;
    float acc = 0.f;
#pragma unroll 8
    for (int l = 0; l < LSPLIT; l++) acc += p[(size_t)l * STRIDE_L];
    g_qpart[(bh * SPLITS + split) * DD + d] = acc;
}

// ---------------- K2: reduce partials -> q_global ----------------
__global__ void k_qred() {
    int bh = blockIdx.x, d = threadIdx.x;
    float acc = 0.f;
#pragma unroll
    for (int s = 0; s < SPLITS; s++) acc += g_qpart[(bh * SPLITS + s) * DD + d];
    g_qglob[bh * DD + d] = acc * (1.0f / (float)LL) * rsqrtf(2048.0f);
}

// ---------------- K3: scores[bh][l] = q_global . K[l] ----------------
__global__ void k_scores(const float* __restrict__ K) {
    __shared__ float4 qg[32];
    int bh = blockIdx.x;
    int tid = threadIdx.x;
    if (tid < 32) qg[tid] = ((const float4*)(g_qglob + bh * DD))[tid];
    __syncthreads();
    int w = tid >> 5, lane = tid & 31;
    int l = blockIdx.y * 8 + w;
    const float4* kp = (const float4*)(K + head_base(bh) + (size_t)l * STRIDE_L);
    float4 kv = kp[lane];
    float4 q  = qg[lane];
    float s = kv.x * q.x + kv.y * q.y + kv.z * q.z + kv.w * q.w;
#pragma unroll
    for (int o = 16; o; o >>= 1) s += __shfl_xor_sync(0xffffffffu, s, o);
    if (lane == 0) g_alpha[bh * LL + l] = s;
}

// ---------------- K4: softmax over L, in-place alpha = exp(s-m)/sum * L ----------------
__global__ void k_softmax() {
    __shared__ float red[256];
    int bh = blockIdx.x, tid = threadIdx.x;
    float* s = g_alpha + bh * LL;
    float m = -1e30f;
    for (int i = tid; i < LL; i += 256) m = fmaxf(m, s[i]);
    red[tid] = m; __syncthreads();
    for (int o = 128; o; o >>= 1) { if (tid < o) red[tid] = fmaxf(red[tid], red[tid + o]); __syncthreads(); }
    m = red[0]; __syncthreads();
    float sum = 0.f;
    for (int i = tid; i < LL; i += 256) {
        float e = expf(s[i] - m);
        s[i] = e;                 // store exp once; rescale in last pass
        sum += e;
    }
    red[tid] = sum; __syncthreads();
    for (int o = 128; o; o >>= 1) { if (tid < o) red[tid] += red[tid + o]; __syncthreads(); }
    float scale = (float)LL / red[0];
    for (int i = tid; i < LL; i += 256) s[i] *= scale;
}

// ---------------- K5: split-K GEMM  KVpart[d][e] = sum_l (alpha[l]*phiK[l][d]) * V[l][e] ----------------
__global__ void __launch_bounds__(256, 2) k_kv(const float* __restrict__ phiK,
                                               const float* __restrict__ V) {
    __shared__ __align__(16) float As[32][PAD];   // alpha-scaled phiK tile [l][d]
    __shared__ __align__(16) float Bs[32][PAD];   // V tile [l][e]
    __shared__ float ks_red[8][DD];

    int split = blockIdx.x, bh = blockIdx.y, tid = threadIdx.x;
    size_t base = head_base(bh);
    int l0 = split * LSPLIT;
    int tx = tid & 15, ty = tid >> 4;
    int ld_d4 = tid & 31;
    int ld_r  = tid >> 5;

    const float* alpha = g_alpha + bh * LL + l0;

    unsigned long long acc2[8][4];                // [i][j2]: cols (tx*4 + 2*j2 ..) packed pairs
#pragma unroll
    for (int i = 0; i < 8; i++)
#pragma unroll
        for (int j = 0; j < 4; j++) acc2[i][j] = 0ULL;
    float ks0 = 0.f, ks1 = 0.f, ks2 = 0.f, ks3 = 0.f;

    for (int t = 0; t < LSPLIT; t += 32) {
        __syncthreads();
#pragma unroll
        for (int j = 0; j < 4; j++) {
            int lr = ld_r + 8 * j;
            int l  = t + lr;
            float a = alpha[l];
            const float* gp = phiK + base + (size_t)(l0 + l) * STRIDE_L + ld_d4 * 4;
            const float* gv = V    + base + (size_t)(l0 + l) * STRIDE_L + ld_d4 * 4;
            float4 pk = *(const float4*)gp;
            pk.x *= a; pk.y *= a; pk.z *= a; pk.w *= a;
            ((float4*)&As[lr][0])[ld_d4] = pk;
            ks0 += pk.x; ks1 += pk.y; ks2 += pk.z; ks3 += pk.w;
            ((float4*)&Bs[lr][0])[ld_d4] = *(const float4*)gv;
        }
        __syncthreads();
#pragma unroll 8
        for (int k = 0; k < 32; k++) {
            float4 a0 = *(const float4*)&As[k][ty * 8];
            float4 a1 = *(const float4*)&As[k][ty * 8 + 4];
            ulonglong2 b0 = *(const ulonglong2*)&Bs[k][tx * 4];
            ulonglong2 b1 = *(const ulonglong2*)&Bs[k][tx * 4 + 64];
            unsigned long long bv[4] = {b0.x, b0.y, b1.x, b1.y};
            float av[8] = {a0.x, a0.y, a0.z, a0.w, a1.x, a1.y, a1.z, a1.w};
#pragma unroll
            for (int i = 0; i < 8; i++) {
                unsigned long long ad = pack2(av[i]);
#pragma unroll
                for (int j = 0; j < 4; j++) ffma2(acc2[i][j], ad, bv[j]);
            }
        }
    }

    // write KV partials: rows ty*8+i (d), packed cols
    float* dstbase = g_kvpart + ((size_t)(bh * SPLITS + split) * DD) * DD;
#pragma unroll
    for (int i = 0; i < 8; i++) {
        float* dst = dstbase + (size_t)(ty * 8 + i) * DD;
        ulonglong2 o0, o1;
        o0.x = acc2[i][0]; o0.y = acc2[i][1];
        o1.x = acc2[i][2]; o1.y = acc2[i][3];
        *(ulonglong2*)(dst + tx * 4)      = o0;
        *(ulonglong2*)(dst + 64 + tx * 4) = o1;
    }

    ((float4*)&ks_red[ld_r][0])[ld_d4] = make_float4(ks0, ks1, ks2, ks3);
    __syncthreads();
    if (tid < 32) {
        float4 s = make_float4(0.f, 0.f, 0.f, 0.f);
#pragma unroll
        for (int r = 0; r < 8; r++) {
            float4 v = ((float4*)&ks_red[r][0])[tid];
            s.x += v.x; s.y += v.y; s.z += v.z; s.w += v.w;
        }
        *(float4*)(g_ksumpart + (bh * SPLITS + split) * DD + tid * 4) = s;
    }
}

// ---------------- K6: reduce split-K partials ----------------
__global__ void k_kvred() {
    int bh = blockIdx.y;
    int idx = blockIdx.x * 1024 + threadIdx.x;
    float acc = 0.f;
#pragma unroll
    for (int s = 0; s < SPLITS; s++)
        acc += g_kvpart[((size_t)(bh * SPLITS + s) * DD) * DD + idx];
    g_kv[(size_t)bh * DD * DD + idx] = acc;
    if (blockIdx.x == 0 && threadIdx.x < DD) {
        float a = 0.f;
#pragma unroll
        for (int s = 0; s < SPLITS; s++) a += g_ksumpart[(bh * SPLITS + s) * DD + threadIdx.x];
        g_ksum[bh * DD + threadIdx.x] = a;
    }
}

// ---------------- K7: out[l][e] = (phiQ[l][:] @ KV[:,e]) / (phiQ[l][:].ksum + eps) ----------------
__global__ void __launch_bounds__(256, 1) k_out(const float* __restrict__ phiQ,
                                                float* __restrict__ out) {
    extern __shared__ __align__(16) float sm[];
    float* KVs = sm;               // [128][PAD]
    float* Qs  = sm + DD * PAD;    // [128][PAD]
    __shared__ float den[DD];
    __shared__ float ks[DD];

    int chunk = blockIdx.x, bh = blockIdx.y, tid = threadIdx.x;
    size_t base = head_base(bh);
    int l0 = chunk * 128;

    const float4* kvsrc = (const float4*)(g_kv + (size_t)bh * DD * DD);
    for (int i = tid; i < DD * DD / 4; i += 256) {
        int r = i >> 5, c4 = i & 31;
        ((float4*)(KVs + r * PAD))[c4] = kvsrc[i];
    }
    if (tid < DD) ks[tid] = g_ksum[bh * DD + tid];
    for (int i = tid; i < 128 * 32; i += 256) {
        int r = i >> 5, c4 = i & 31;
        ((float4*)(Qs + r * PAD))[c4] =
            *(const float4*)(phiQ + base + (size_t)(l0 + r) * STRIDE_L + c4 * 4);
    }
    __syncthreads();

    {
        int w = tid >> 5, lane = tid & 31;
        for (int r = w * 16; r < w * 16 + 16; r++) {
            float4 q = ((const float4*)(Qs + r * PAD))[lane];
            float4 k4 = ((const float4*)ks)[lane];
            float d = q.x * k4.x + q.y * k4.y + q.z * k4.z + q.w * k4.w;
#pragma unroll
            for (int o = 16; o; o >>= 1) d += __shfl_xor_sync(0xffffffffu, d, o);
            if (lane == 0) den[r] = d + EPS;
        }
    }
    __syncthreads();

    int tx = tid & 15, ty = tid >> 4;
    unsigned long long acc2[8][4];
#pragma unroll
    for (int i = 0; i < 8; i++)
#pragma unroll
        for (int j = 0; j < 4; j++) acc2[i][j] = 0ULL;

#pragma unroll 8
    for (int k = 0; k < DD; k++) {
        float av[8];
#pragma unroll
        for (int i = 0; i < 8; i++) av[i] = Qs[(ty * 8 + i) * PAD + k];
        ulonglong2 b0 = *(const ulonglong2*)(KVs + k * PAD + tx * 4);
        ulonglong2 b1 = *(const ulonglong2*)(KVs + k * PAD + 64 + tx * 4);
        unsigned long long bv[4] = {b0.x, b0.y, b1.x, b1.y};
#pragma unroll
        for (int i = 0; i < 8; i++) {
            unsigned long long ad = pack2(av[i]);
#pragma unroll
            for (int j = 0; j < 4; j++) ffma2(acc2[i][j], ad, bv[j]);
        }
    }

#pragma unroll
    for (int i = 0; i < 8; i++) {
        int l = ty * 8 + i;
        unsigned long long dinv2 = pack2(1.0f / den[l]);
        float* dst = out + base + (size_t)(l0 + l) * STRIDE_L;
        ulonglong2 o0, o1;
        o0.x = mul2(acc2[i][0], dinv2); o0.y = mul2(acc2[i][1], dinv2);
        o1.x = mul2(acc2[i][2], dinv2); o1.y = mul2(acc2[i][3], dinv2);
        *(ulonglong2*)(dst + tx * 4)      = o0;
        *(ulonglong2*)(dst + 64 + tx * 4) = o1;
    }
}

// ---------------- launch ----------------
extern "C" void kernel_launch(void* const* d_in, const int* in_sizes, int n_in,
                              void* d_out, int out_size) {
    const float* Q    = (const float*)d_in[0];
    const float* K    = (const float*)d_in[1];
    const float* V    = (const float*)d_in[2];
    const float* phiQ = (const float*)d_in[3];
    const float* phiK = (const float*)d_in[4];
    float* out = (float*)d_out;

    static bool attr_set = false;
    if (!attr_set) {
        cudaFuncSetAttribute(k_out, cudaFuncAttributeMaxDynamicSharedMemorySize,
                             2 * DD * PAD * (int)sizeof(float));
        attr_set = true;
    }

    k_qsum<<<dim3(SPLITS, BH), 128>>>(Q);
    k_qred<<<BH, 128>>>();
    k_scores<<<dim3(BH, LL / 8), 256>>>(K);
    k_softmax<<<BH, 256>>>();
    k_kv<<<dim3(SPLITS, BH), 256>>>(phiK, V);
    k_kvred<<<dim3(16, BH), 1024>>>();
    k_out<<<dim3(LL / 128, BH), 256, 2 * DD * PAD * (int)sizeof(float)>>>(phiQ, out);
}

// round 6
// speedup vs baseline: 1.3119x; 1.2764x over previous
#include <cuda_runtime.h>
#include <cuda_bf16.h>
#include <cstdint>

#define BB 4
#define LL 4096
#define HH 16
#define DD 128
#define BH (BB*HH)
#define SPLITS 8
#define LSPLIT (LL/SPLITS)
#define STRIDE_L (HH*DD)
#define EPS 1e-6f

// ---------------- scratch ----------------
__device__ float g_qpart[BH*SPLITS*DD];
__device__ float g_qglob[BH*DD];
__device__ float g_alpha[BH*LL];
__device__ float g_kvpart[(size_t)BH*SPLITS*DD*DD];
__device__ float g_ksumpart[BH*64*DD];
__device__ float g_ksum[BH*DD];
__device__ unsigned g_phiKT_hi[(size_t)BH*DD*(LL/2)];   // [bh][d][l/2] bf16x2
__device__ unsigned g_phiKT_lo[(size_t)BH*DD*(LL/2)];
__device__ unsigned g_vT_hi[(size_t)BH*DD*(LL/2)];      // [bh][e][l/2]
__device__ unsigned g_vT_lo[(size_t)BH*DD*(LL/2)];
__device__ unsigned g_kvT_hi[BH*DD*(DD/2)];             // [bh][e][d/2]
__device__ unsigned g_kvT_lo[BH*DD*(DD/2)];

__device__ __forceinline__ size_t head_base(int bh) {
    return (size_t)(bh >> 4) * LL * STRIDE_L + (size_t)(bh & 15) * DD;
}
__device__ __forceinline__ unsigned smem_u32(const void* p) {
    unsigned a;
    asm("{ .reg .u64 t; cvta.to.shared.u64 t, %1; cvt.u32.u64 %0, t; }" : "=r"(a) : "l"(p));
    return a;
}
__device__ __forceinline__ unsigned sw(unsigned off) { return off ^ ((off >> 3) & 0x70); }
__device__ __forceinline__ void cvt_hilo(float x, unsigned short& h, unsigned short& l) {
    __nv_bfloat16 b = __float2bfloat16_rn(x);
    h = __bfloat16_as_ushort(b);
    l = __bfloat16_as_ushort(__float2bfloat16_rn(x - __bfloat162float(b)));
}
__device__ __forceinline__ void ldsm4(unsigned r[4], unsigned addr) {
    asm volatile("ldmatrix.sync.aligned.m8n8.x4.shared.b16 {%0,%1,%2,%3}, [%4];"
        : "=r"(r[0]), "=r"(r[1]), "=r"(r[2]), "=r"(r[3]) : "r"(addr));
}
__device__ __forceinline__ void mma16816(float c[4], const unsigned a[4], unsigned b0, unsigned b1) {
    asm volatile("mma.sync.aligned.m16n8k16.row.col.f32.bf16.bf16.f32 "
        "{%0,%1,%2,%3}, {%4,%5,%6,%7}, {%8,%9}, {%0,%1,%2,%3};"
        : "+f"(c[0]), "+f"(c[1]), "+f"(c[2]), "+f"(c[3])
        : "r"(a[0]), "r"(a[1]), "r"(a[2]), "r"(a[3]), "r"(b0), "r"(b1));
}

// ---------------- K1/K2: q_global ----------------
__global__ void k_qsum(const float* __restrict__ Q) {
    int split = blockIdx.x, bh = blockIdx.y, d = threadIdx.x;
    const float* p = Q + head_base(bh) + (size_t)split * LSPLIT * STRIDE_L + d;
    float acc = 0.f;
#pragma unroll 8
    for (int l = 0; l < LSPLIT; l++) acc += p[(size_t)l * STRIDE_L];
    g_qpart[(bh * SPLITS + split) * DD + d] = acc;
}
__global__ void k_qred() {
    int bh = blockIdx.x, d = threadIdx.x;
    float acc = 0.f;
#pragma unroll
    for (int s = 0; s < SPLITS; s++) acc += g_qpart[(bh * SPLITS + s) * DD + d];
    g_qglob[bh * DD + d] = acc * (1.0f / (float)LL) * rsqrtf(2048.0f);
}

// ---------------- K3: scores ----------------
__global__ void k_scores(const float* __restrict__ K) {
    __shared__ float4 qg[32];
    int bh = blockIdx.x, tid = threadIdx.x;
    if (tid < 32) qg[tid] = ((const float4*)(g_qglob + bh * DD))[tid];
    __syncthreads();
    int w = tid >> 5, lane = tid & 31;
    int l = blockIdx.y * 8 + w;
    const float4* kp = (const float4*)(K + head_base(bh) + (size_t)l * STRIDE_L);
    float4 kv = kp[lane];
    float4 q = qg[lane];
    float s = kv.x * q.x + kv.y * q.y + kv.z * q.z + kv.w * q.w;
#pragma unroll
    for (int o = 16; o; o >>= 1) s += __shfl_xor_sync(0xffffffffu, s, o);
    if (lane == 0) g_alpha[bh * LL + l] = s;
}

// ---------------- K4: softmax ----------------
__global__ void k_softmax() {
    __shared__ float red[256];
    int bh = blockIdx.x, tid = threadIdx.x;
    float* s = g_alpha + bh * LL;
    float m = -1e30f;
    for (int i = tid; i < LL; i += 256) m = fmaxf(m, s[i]);
    red[tid] = m; __syncthreads();
    for (int o = 128; o; o >>= 1) { if (tid < o) red[tid] = fmaxf(red[tid], red[tid + o]); __syncthreads(); }
    m = red[0]; __syncthreads();
    float sum = 0.f;
    for (int i = tid; i < LL; i += 256) { float e = expf(s[i] - m); s[i] = e; sum += e; }
    red[tid] = sum; __syncthreads();
    for (int o = 128; o; o >>= 1) { if (tid < o) red[tid] += red[tid + o]; __syncthreads(); }
    float scale = (float)LL / red[0];
    for (int i = tid; i < LL; i += 256) s[i] *= scale;
}

// ---------------- P: transpose + optional alpha + bf16 hi/lo split ----------------
// grid (LL/64, BH), block 256, dyn smem 68608
template<bool SCALED>
__global__ void __launch_bounds__(256) p_trans(const float* __restrict__ src) {
    extern __shared__ __align__(16) unsigned char smb[];
    float* in = (float*)smb;                                  // [64][132]
    unsigned* oh = (unsigned*)(smb + 64*132*4);               // [128][33]
    unsigned* ol = (unsigned*)(smb + 64*132*4 + 128*33*4);
    float* ksr = (float*)(smb + 64*132*4 + 2*128*33*4);       // [2][128]

    int lt = blockIdx.x, bh = blockIdx.y, tid = threadIdx.x;
    size_t base = head_base(bh);
    int l0 = lt * 64;

    for (int idx = tid; idx < 2048; idx += 256) {
        int l = idx >> 5, d4 = idx & 31;
        float4 v = *(const float4*)(src + base + (size_t)(l0 + l) * STRIDE_L + d4 * 4);
        if (SCALED) {
            float a = g_alpha[bh * LL + l0 + l];
            v.x *= a; v.y *= a; v.z *= a; v.w *= a;
        }
        *(float4*)&in[l * 132 + d4 * 4] = v;
    }
    __syncthreads();

    int d = tid >> 1, half = tid & 1;
    float ks = 0.f;
#pragma unroll 4
    for (int i = 0; i < 16; i++) {
        int l = half * 32 + 2 * i;
        float x0 = in[l * 132 + d], x1 = in[(l + 1) * 132 + d];
        if (SCALED) ks += x0 + x1;
        unsigned short h0, q0, h1, q1;
        cvt_hilo(x0, h0, q0); cvt_hilo(x1, h1, q1);
        oh[d * 33 + half * 16 + i] = (unsigned)h0 | ((unsigned)h1 << 16);
        ol[d * 33 + half * 16 + i] = (unsigned)q0 | ((unsigned)q1 << 16);
    }
    if (SCALED) ksr[half * 128 + d] = ks;
    __syncthreads();
    if (SCALED && tid < 128)
        g_ksumpart[(bh * 64 + lt) * DD + tid] = ksr[tid] + ksr[128 + tid];

    unsigned* dh = SCALED ? g_phiKT_hi : g_vT_hi;
    unsigned* dl = SCALED ? g_phiKT_lo : g_vT_lo;
    for (int idx = tid; idx < 4096; idx += 256) {
        int r = idx >> 5, c = idx & 31;
        size_t di = (size_t)(bh * DD + r) * (LL/2) + (l0 >> 1) + c;
        dh[di] = oh[r * 33 + c];
        dl[di] = ol[r * 33 + c];
    }
}

// ---------------- K5: HMMA split-K GEMM -> kvpart ----------------
// grid (SPLITS, BH), block 256 (8 warps), dyn smem 65536
// SMEM: Ahi[128][64]bf16 @0, Alo @16K, Bhi @32K, Blo @48K (128B rows, SW128)
__global__ void __launch_bounds__(256, 2) k5_gemm() {
    extern __shared__ __align__(16) unsigned char smb[];
    unsigned sbase = smem_u32(smb);
    const int ALO = 16384, BHI = 32768, BLO = 49152;

    int split = blockIdx.x, bh = blockIdx.y, tid = threadIdx.x;
    int wid = tid >> 5, lane = tid & 31;
    int warpM = (wid >> 1) * 32, warpN = (wid & 1) * 64;

    float acc[2][8][4];
#pragma unroll
    for (int mt = 0; mt < 2; mt++)
#pragma unroll
        for (int nt = 0; nt < 8; nt++)
#pragma unroll
            for (int c = 0; c < 4; c++) acc[mt][nt][c] = 0.f;

    for (int ch = 0; ch < 8; ch++) {
        int lp = (split * LSPLIT + ch * 64) >> 1;
        for (int idx = tid; idx < 1024; idx += 256) {
            int row = idx >> 3, c8 = idx & 7;
            size_t src = (size_t)(bh * DD + row) * (LL/2) + lp + c8 * 4;
            unsigned off = sw(row * 128 + c8 * 16);
            *(uint4*)(smb + off)        = *(const uint4*)(g_phiKT_hi + src);
            *(uint4*)(smb + ALO + off)  = *(const uint4*)(g_phiKT_lo + src);
            *(uint4*)(smb + BHI + off)  = *(const uint4*)(g_vT_hi + src);
            *(uint4*)(smb + BLO + off)  = *(const uint4*)(g_vT_lo + src);
        }
        __syncthreads();
#pragma unroll
        for (int ks = 0; ks < 4; ks++) {
            unsigned ah[2][4], al[2][4];
#pragma unroll
            for (int mt = 0; mt < 2; mt++) {
                unsigned aoff = sw((warpM + mt * 16 + (lane & 15)) * 128 + ks * 32 + (lane >> 4) * 16);
                ldsm4(ah[mt], sbase + aoff);
                ldsm4(al[mt], sbase + ALO + aoff);
            }
#pragma unroll
            for (int np = 0; np < 4; np++) {
                unsigned bhr[4], blr[4];
                unsigned boff = sw((warpN + (np * 2 + (lane >> 4)) * 8 + (lane & 7)) * 128
                                   + ks * 32 + ((lane >> 3) & 1) * 16);
                ldsm4(bhr, sbase + BHI + boff);
                ldsm4(blr, sbase + BLO + boff);
#pragma unroll
                for (int mt = 0; mt < 2; mt++) {
                    mma16816(acc[mt][np*2],   ah[mt], bhr[0], bhr[1]);
                    mma16816(acc[mt][np*2],   al[mt], bhr[0], bhr[1]);
                    mma16816(acc[mt][np*2],   ah[mt], blr[0], blr[1]);
                    mma16816(acc[mt][np*2+1], ah[mt], bhr[2], bhr[3]);
                    mma16816(acc[mt][np*2+1], al[mt], bhr[2], bhr[3]);
                    mma16816(acc[mt][np*2+1], ah[mt], blr[2], blr[3]);
                }
            }
        }
        __syncthreads();
    }

    float* dstb = g_kvpart + (size_t)(bh * SPLITS + split) * DD * DD;
    int g = lane >> 2, qc = (lane & 3) * 2;
#pragma unroll
    for (int mt = 0; mt < 2; mt++)
#pragma unroll
        for (int nt = 0; nt < 8; nt++) {
            int row = warpM + mt * 16 + g;
            int col = warpN + nt * 8 + qc;
            *(float2*)&dstb[(size_t)row * DD + col]       = make_float2(acc[mt][nt][0], acc[mt][nt][1]);
            *(float2*)&dstb[(size_t)(row + 8) * DD + col] = make_float2(acc[mt][nt][2], acc[mt][nt][3]);
        }
}

// ---------------- K6: reduce partials -> ksum + KVT bf16 hi/lo ----------------
// grid BH, block 256, dyn smem 132608
__global__ void __launch_bounds__(256) k6_reduce() {
    extern __shared__ __align__(16) unsigned char smb[];
    float* acc = (float*)smb;                            // [128][129]
    unsigned* oh = (unsigned*)(smb + 128*129*4);         // [128][65]
    unsigned* ol = (unsigned*)(smb + 128*129*4 + 128*65*4);

    int bh = blockIdx.x, tid = threadIdx.x;
    for (int idx = tid; idx < DD * DD; idx += 256) {
        float s = 0.f;
#pragma unroll
        for (int sp = 0; sp < SPLITS; sp++)
            s += g_kvpart[(size_t)(bh * SPLITS + sp) * DD * DD + idx];
        acc[(idx >> 7) * 129 + (idx & 127)] = s;
    }
    if (tid < DD) {
        float s = 0.f;
#pragma unroll 8
        for (int t = 0; t < 64; t++) s += g_ksumpart[(bh * 64 + t) * DD + tid];
        g_ksum[bh * DD + tid] = s;
    }
    __syncthreads();
    int e = tid >> 1, half = tid & 1;
#pragma unroll 4
    for (int i = 0; i < 32; i++) {
        int d = half * 64 + 2 * i;
        float x0 = acc[d * 129 + e], x1 = acc[(d + 1) * 129 + e];
        unsigned short h0, q0, h1, q1;
        cvt_hilo(x0, h0, q0); cvt_hilo(x1, h1, q1);
        oh[e * 65 + half * 32 + i] = (unsigned)h0 | ((unsigned)h1 << 16);
        ol[e * 65 + half * 32 + i] = (unsigned)q0 | ((unsigned)q1 << 16);
    }
    __syncthreads();
    for (int idx = tid; idx < 8192; idx += 256) {
        int r = idx >> 6, c = idx & 63;
        size_t di = (size_t)(bh * DD + r) * (DD/2) + c;
        g_kvT_hi[di] = oh[r * 65 + c];
        g_kvT_lo[di] = ol[r * 65 + c];
    }
}

// ---------------- K7: HMMA GEMM out = phiQ @ KV / den ----------------
// grid (LL/128, BH), block 256, dyn smem 65536
__global__ void __launch_bounds__(256, 2) k7_gemm(const float* __restrict__ phiQ,
                                                  float* __restrict__ out) {
    extern __shared__ __align__(16) unsigned char smb[];
    unsigned sbase = smem_u32(smb);
    __shared__ float sden[DD];
    __shared__ float ksp[DD];
    const int ALO = 16384, BHI = 32768, BLO = 49152;

    int chunk = blockIdx.x, bh = blockIdx.y, tid = threadIdx.x;
    int wid = tid >> 5, lane = tid & 31;
    int warpM = (wid >> 1) * 32, warpN = (wid & 1) * 64;
    size_t base = head_base(bh);
    int l0 = chunk * 128;

    if (tid < DD) ksp[tid] = g_ksum[bh * DD + tid];
    __syncthreads();

    float acc[2][8][4];
#pragma unroll
    for (int mt = 0; mt < 2; mt++)
#pragma unroll
        for (int nt = 0; nt < 8; nt++)
#pragma unroll
            for (int c = 0; c < 4; c++) acc[mt][nt][c] = 0.f;
    float denAcc[8];
#pragma unroll
    for (int i = 0; i < 8; i++) denAcc[i] = 0.f;

    for (int ch = 0; ch < 2; ch++) {
        // B: KVT[e][d-chunk]
        for (int idx = tid; idx < 1024; idx += 256) {
            int row = idx >> 3, c8 = idx & 7;
            size_t src = (size_t)(bh * DD + row) * (DD/2) + ch * 32 + c8 * 4;
            unsigned off = sw(row * 128 + c8 * 16);
            *(uint4*)(smb + BHI + off) = *(const uint4*)(g_kvT_hi + src);
            *(uint4*)(smb + BLO + off) = *(const uint4*)(g_kvT_lo + src);
        }
        // A: phiQ fp32 -> hi/lo, den partials fused
#pragma unroll
        for (int it = 0; it < 8; it++) {
            int idx = tid + it * 256;
            int row = idx >> 4, c4 = idx & 15;
            int dg = ch * 64 + c4 * 4;
            float4 v = *(const float4*)(phiQ + base + (size_t)(l0 + row) * STRIDE_L + dg);
            float p = v.x * ksp[dg] + v.y * ksp[dg+1] + v.z * ksp[dg+2] + v.w * ksp[dg+3];
#pragma unroll
            for (int o = 8; o; o >>= 1) p += __shfl_xor_sync(0xffffffffu, p, o);
            denAcc[it] += p;
            unsigned short h0, q0, h1, q1, h2, q2, h3, q3;
            cvt_hilo(v.x, h0, q0); cvt_hilo(v.y, h1, q1);
            cvt_hilo(v.z, h2, q2); cvt_hilo(v.w, h3, q3);
            unsigned off = sw((unsigned)(row * 128 + c4 * 8));
            *(uint2*)(smb + off)       = make_uint2((unsigned)h0 | ((unsigned)h1 << 16),
                                                    (unsigned)h2 | ((unsigned)h3 << 16));
            *(uint2*)(smb + ALO + off) = make_uint2((unsigned)q0 | ((unsigned)q1 << 16),
                                                    (unsigned)q2 | ((unsigned)q3 << 16));
        }
        __syncthreads();
#pragma unroll
        for (int ks = 0; ks < 4; ks++) {
            unsigned ah[2][4], al[2][4];
#pragma unroll
            for (int mt = 0; mt < 2; mt++) {
                unsigned aoff = sw((warpM + mt * 16 + (lane & 15)) * 128 + ks * 32 + (lane >> 4) * 16);
                ldsm4(ah[mt], sbase + aoff);
                ldsm4(al[mt], sbase + ALO + aoff);
            }
#pragma unroll
            for (int np = 0; np < 4; np++) {
                unsigned bhr[4], blr[4];
                unsigned boff = sw((warpN + (np * 2 + (lane >> 4)) * 8 + (lane & 7)) * 128
                                   + ks * 32 + ((lane >> 3) & 1) * 16);
                ldsm4(bhr, sbase + BHI + boff);
                ldsm4(blr, sbase + BLO + boff);
#pragma unroll
                for (int mt = 0; mt < 2; mt++) {
                    mma16816(acc[mt][np*2],   ah[mt], bhr[0], bhr[1]);
                    mma16816(acc[mt][np*2],   al[mt], bhr[0], bhr[1]);
                    mma16816(acc[mt][np*2],   ah[mt], blr[0], blr[1]);
                    mma16816(acc[mt][np*2+1], ah[mt], bhr[2], bhr[3]);
                    mma16816(acc[mt][np*2+1], al[mt], bhr[2], bhr[3]);
                    mma16816(acc[mt][np*2+1], ah[mt], blr[2], blr[3]);
                }
            }
        }
        __syncthreads();
    }
    if ((tid & 15) == 0) {
#pragma unroll
        for (int it = 0; it < 8; it++) sden[(tid >> 4) + it * 16] = denAcc[it] + EPS;
    }
    __syncthreads();

    int g = lane >> 2, qc = (lane & 3) * 2;
#pragma unroll
    for (int mt = 0; mt < 2; mt++) {
        int row = warpM + mt * 16 + g;
        float d0 = 1.0f / sden[row], d1 = 1.0f / sden[row + 8];
#pragma unroll
        for (int nt = 0; nt < 8; nt++) {
            int col = warpN + nt * 8 + qc;
            float* p0 = out + base + (size_t)(l0 + row) * STRIDE_L + col;
            float* p1 = out + base + (size_t)(l0 + row + 8) * STRIDE_L + col;
            *(float2*)p0 = make_float2(acc[mt][nt][0] * d0, acc[mt][nt][1] * d0);
            *(float2*)p1 = make_float2(acc[mt][nt][2] * d1, acc[mt][nt][3] * d1);
        }
    }
}

// ---------------- launch ----------------
extern "C" void kernel_launch(void* const* d_in, const int* in_sizes, int n_in,
                              void* d_out, int out_size) {
    const float* Q    = (const float*)d_in[0];
    const float* K    = (const float*)d_in[1];
    const float* V    = (const float*)d_in[2];
    const float* phiQ = (const float*)d_in[3];
    const float* phiK = (const float*)d_in[4];
    float* out = (float*)d_out;

    static bool attr_set = false;
    if (!attr_set) {
        cudaFuncSetAttribute(p_trans<true>,  cudaFuncAttributeMaxDynamicSharedMemorySize, 68608);
        cudaFuncSetAttribute(p_trans<false>, cudaFuncAttributeMaxDynamicSharedMemorySize, 68608);
        cudaFuncSetAttribute(k5_gemm,   cudaFuncAttributeMaxDynamicSharedMemorySize, 65536);
        cudaFuncSetAttribute(k6_reduce, cudaFuncAttributeMaxDynamicSharedMemorySize, 132608);
        cudaFuncSetAttribute(k7_gemm,   cudaFuncAttributeMaxDynamicSharedMemorySize, 65536);
        attr_set = true;
    }

    k_qsum<<<dim3(SPLITS, BH), 128>>>(Q);
    k_qred<<<BH, 128>>>();
    k_scores<<<dim3(BH, LL / 8), 256>>>(K);
    p_trans<false><<<dim3(LL/64, BH), 256, 68608>>>(V);
    k_softmax<<<BH, 256>>>();
    p_trans<true><<<dim3(LL/64, BH), 256, 68608>>>(phiK);
    k5_gemm<<<dim3(SPLITS, BH), 256, 65536>>>();
    k6_reduce<<<BH, 256, 132608>>>();
    k7_gemm<<<dim3(LL/128, BH), 256, 65536>>>(phiQ, out);
}

// round 8
// speedup vs baseline: 1.6346x; 1.2460x over previous
#include <cuda_runtime.h>
#include <cuda_bf16.h>
#include <cstdint>

#define BB 4
#define LL 4096
#define HH 16
#define DD 128
#define BH (BB*HH)
#define SPLITS 8
#define LSPLIT (LL/SPLITS)
#define STRIDE_L (HH*DD)
#define EPS 1e-6f

// ---------------- scratch ----------------
__device__ float g_qpart[BH*SPLITS*DD];
__device__ float g_qglob[BH*DD];
__device__ float g_alpha[BH*LL];
__device__ float g_kvpart[(size_t)BH*SPLITS*DD*DD];
__device__ float g_ksumpart[BH*SPLITS*DD];
__device__ float g_ksum[BH*DD];
__device__ unsigned g_kvT_hi[BH*DD*(DD/2)];             // [bh][e][d/2]
__device__ unsigned g_kvT_lo[BH*DD*(DD/2)];

__device__ __forceinline__ size_t head_base(int bh) {
    return (size_t)(bh >> 4) * LL * STRIDE_L + (size_t)(bh & 15) * DD;
}
__device__ __forceinline__ unsigned smem_u32(const void* p) {
    unsigned a;
    asm("{ .reg .u64 t; cvta.to.shared.u64 t, %1; cvt.u32.u64 %0, t; }" : "=r"(a) : "l"(p));
    return a;
}
__device__ __forceinline__ unsigned sw(unsigned off)   { return off ^ ((off >> 3) & 0x70); }      // 128B rows
__device__ __forceinline__ unsigned swz256(unsigned off){ return off ^ (((off >> 8) & 7) << 4); } // 256B rows
__device__ __forceinline__ void cvt_hilo(float x, unsigned short& h, unsigned short& l) {
    __nv_bfloat16 b = __float2bfloat16_rn(x);
    h = __bfloat16_as_ushort(b);
    l = __bfloat16_as_ushort(__float2bfloat16_rn(x - __bfloat162float(b)));
}
__device__ __forceinline__ void ldsm4(unsigned r[4], unsigned addr) {
    asm volatile("ldmatrix.sync.aligned.m8n8.x4.shared.b16 {%0,%1,%2,%3}, [%4];"
        : "=r"(r[0]), "=r"(r[1]), "=r"(r[2]), "=r"(r[3]) : "r"(addr));
}
__device__ __forceinline__ void ldsm4t(unsigned r[4], unsigned addr) {
    asm volatile("ldmatrix.sync.aligned.m8n8.x4.trans.shared.b16 {%0,%1,%2,%3}, [%4];"
        : "=r"(r[0]), "=r"(r[1]), "=r"(r[2]), "=r"(r[3]) : "r"(addr));
}
__device__ __forceinline__ void mma16816(float c[4], const unsigned a[4], unsigned b0, unsigned b1) {
    asm volatile("mma.sync.aligned.m16n8k16.row.col.f32.bf16.bf16.f32 "
        "{%0,%1,%2,%3}, {%4,%5,%6,%7}, {%8,%9}, {%0,%1,%2,%3};"
        : "+f"(c[0]), "+f"(c[1]), "+f"(c[2]), "+f"(c[3])
        : "r"(a[0]), "r"(a[1]), "r"(a[2]), "r"(a[3]), "r"(b0), "r"(b1));
}

// ---------------- K1/K2: q_global ----------------
__global__ void k_qsum(const float* __restrict__ Q) {
    int split = blockIdx.x, bh = blockIdx.y, d = threadIdx.x;
    const float* p = Q + head_base(bh) + (size_t)split * LSPLIT * STRIDE_L + d;
    float acc = 0.f;
#pragma unroll 8
    for (int l = 0; l < LSPLIT; l++) acc += p[(size_t)l * STRIDE_L];
    g_qpart[(bh * SPLITS + split) * DD + d] = acc;
}
__global__ void k_qred() {
    int bh = blockIdx.x, d = threadIdx.x;
    float acc = 0.f;
#pragma unroll
    for (int s = 0; s < SPLITS; s++) acc += g_qpart[(bh * SPLITS + s) * DD + d];
    g_qglob[bh * DD + d] = acc * (1.0f / (float)LL) * rsqrtf(2048.0f);
}

// ---------------- K3: scores ----------------
__global__ void k_scores(const float* __restrict__ K) {
    __shared__ float4 qg[32];
    int bh = blockIdx.x, tid = threadIdx.x;
    if (tid < 32) qg[tid] = ((const float4*)(g_qglob + bh * DD))[tid];
    __syncthreads();
    int w = tid >> 5, lane = tid & 31;
    int l = blockIdx.y * 8 + w;
    const float4* kp = (const float4*)(K + head_base(bh) + (size_t)l * STRIDE_L);
    float4 kv = kp[lane];
    float4 q = qg[lane];
    float s = kv.x * q.x + kv.y * q.y + kv.z * q.z + kv.w * q.w;
#pragma unroll
    for (int o = 16; o; o >>= 1) s += __shfl_xor_sync(0xffffffffu, s, o);
    if (lane == 0) g_alpha[bh * LL + l] = s;
}

// ---------------- K4: softmax ----------------
__global__ void k_softmax() {
    __shared__ float red[256];
    int bh = blockIdx.x, tid = threadIdx.x;
    float* s = g_alpha + bh * LL;
    float m = -1e30f;
    for (int i = tid; i < LL; i += 256) m = fmaxf(m, s[i]);
    red[tid] = m; __syncthreads();
    for (int o = 128; o; o >>= 1) { if (tid < o) red[tid] = fmaxf(red[tid], red[tid + o]); __syncthreads(); }
    m = red[0]; __syncthreads();
    float sum = 0.f;
    for (int i = tid; i < LL; i += 256) { float e = expf(s[i] - m); s[i] = e; sum += e; }
    red[tid] = sum; __syncthreads();
    for (int o = 128; o; o >>= 1) { if (tid < o) red[tid] += red[tid + o]; __syncthreads(); }
    float scale = (float)LL / red[0];
    for (int i = tid; i < LL; i += 256) s[i] *= scale;
}

// ---------------- K5: fused load+convert+transpose HMMA split-K GEMM ----------------
// grid (SPLITS, BH), block 256 (8 warps), dyn smem 69632
// SMEM [64 l][128]bf16 tiles (256B rows, swz256): Ahi@0 Alo@16K Bhi@32K Blo@48K, ksred@64K
__global__ void __launch_bounds__(256, 2) k5_gemm(const float* __restrict__ phiK,
                                                  const float* __restrict__ V) {
    extern __shared__ __align__(16) unsigned char smb[];
    unsigned sbase = smem_u32(smb);
    const int ALO = 16384, BHI = 32768, BLO = 49152, KSR = 65536;

    int split = blockIdx.x, bh = blockIdx.y, tid = threadIdx.x;
    int wid = tid >> 5, lane = tid & 31;
    int warpM = (wid >> 1) * 32, warpN = (wid & 1) * 64;
    size_t base = head_base(bh);
    int d4 = tid & 31, lrow = tid >> 5;

    float acc[2][8][4];
#pragma unroll
    for (int mt = 0; mt < 2; mt++)
#pragma unroll
        for (int nt = 0; nt < 8; nt++)
#pragma unroll
            for (int c = 0; c < 4; c++) acc[mt][nt][c] = 0.f;
    float ksa[4] = {0.f, 0.f, 0.f, 0.f};

    for (int ch = 0; ch < 8; ch++) {
        int lbase = split * LSPLIT + ch * 64;
        __syncthreads();
#pragma unroll
        for (int it = 0; it < 8; it++) {
            int l = lrow + it * 8;
            float a = g_alpha[bh * LL + lbase + l];
            const float* gp = phiK + base + (size_t)(lbase + l) * STRIDE_L + d4 * 4;
            const float* gv = V    + base + (size_t)(lbase + l) * STRIDE_L + d4 * 4;
            float4 pk = *(const float4*)gp;
            pk.x *= a; pk.y *= a; pk.z *= a; pk.w *= a;
            ksa[0] += pk.x; ksa[1] += pk.y; ksa[2] += pk.z; ksa[3] += pk.w;
            unsigned short h0,q0,h1,q1,h2,q2,h3,q3;
            cvt_hilo(pk.x,h0,q0); cvt_hilo(pk.y,h1,q1); cvt_hilo(pk.z,h2,q2); cvt_hilo(pk.w,h3,q3);
            unsigned off = swz256((unsigned)(l * 256 + d4 * 8));
            *(uint2*)(smb + off)       = make_uint2((unsigned)h0 | ((unsigned)h1 << 16),
                                                    (unsigned)h2 | ((unsigned)h3 << 16));
            *(uint2*)(smb + ALO + off) = make_uint2((unsigned)q0 | ((unsigned)q1 << 16),
                                                    (unsigned)q2 | ((unsigned)q3 << 16));
            float4 vv = *(const float4*)gv;
            cvt_hilo(vv.x,h0,q0); cvt_hilo(vv.y,h1,q1); cvt_hilo(vv.z,h2,q2); cvt_hilo(vv.w,h3,q3);
            *(uint2*)(smb + BHI + off) = make_uint2((unsigned)h0 | ((unsigned)h1 << 16),
                                                    (unsigned)h2 | ((unsigned)h3 << 16));
            *(uint2*)(smb + BLO + off) = make_uint2((unsigned)q0 | ((unsigned)q1 << 16),
                                                    (unsigned)q2 | ((unsigned)q3 << 16));
        }
        __syncthreads();
#pragma unroll
        for (int kk = 0; kk < 4; kk++) {
            unsigned ah[2][4], al[2][4];
#pragma unroll
            for (int mt = 0; mt < 2; mt++) {
                unsigned row = kk * 16 + ((lane >> 4) & 1) * 8 + (lane & 7);
                unsigned col = (warpM + mt * 16) * 2 + ((lane >> 3) & 1) * 16;
                unsigned aoff = swz256(row * 256 + col);
                ldsm4t(ah[mt], sbase + aoff);
                ldsm4t(al[mt], sbase + ALO + aoff);
            }
#pragma unroll
            for (int np = 0; np < 4; np++) {
                unsigned bhr[4], blr[4];
                unsigned brow = kk * 16 + ((lane >> 3) & 1) * 8 + (lane & 7);
                unsigned bcol = (warpN + np * 16) * 2 + ((lane >> 4) & 1) * 16;
                unsigned boff = swz256(brow * 256 + bcol);
                ldsm4t(bhr, sbase + BHI + boff);
                ldsm4t(blr, sbase + BLO + boff);
#pragma unroll
                for (int mt = 0; mt < 2; mt++) {
                    mma16816(acc[mt][np*2],   ah[mt], bhr[0], bhr[1]);
                    mma16816(acc[mt][np*2],   al[mt], bhr[0], bhr[1]);
                    mma16816(acc[mt][np*2],   ah[mt], blr[0], blr[1]);
                    mma16816(acc[mt][np*2+1], ah[mt], bhr[2], bhr[3]);
                    mma16816(acc[mt][np*2+1], al[mt], bhr[2], bhr[3]);
                    mma16816(acc[mt][np*2+1], ah[mt], blr[2], blr[3]);
                }
            }
        }
    }
    __syncthreads();

    // kvpart epilogue
    float* dstb = g_kvpart + (size_t)(bh * SPLITS + split) * DD * DD;
    int g = lane >> 2, qc = (lane & 3) * 2;
#pragma unroll
    for (int mt = 0; mt < 2; mt++)
#pragma unroll
        for (int nt = 0; nt < 8; nt++) {
            int row = warpM + mt * 16 + g;
            int col = warpN + nt * 8 + qc;
            *(float2*)&dstb[(size_t)row * DD + col]       = make_float2(acc[mt][nt][0], acc[mt][nt][1]);
            *(float2*)&dstb[(size_t)(row + 8) * DD + col] = make_float2(acc[mt][nt][2], acc[mt][nt][3]);
        }

    // ksum partial: reduce over the 8 lrow groups
    *(float4*)(smb + KSR + (lrow * DD + d4 * 4) * 4) = make_float4(ksa[0], ksa[1], ksa[2], ksa[3]);
    __syncthreads();
    if (tid < 32) {
        float4 s = make_float4(0.f, 0.f, 0.f, 0.f);
#pragma unroll
        for (int r = 0; r < 8; r++) {
            float4 v = *(float4*)(smb + KSR + (r * DD + tid * 4) * 4);
            s.x += v.x; s.y += v.y; s.z += v.z; s.w += v.w;
        }
        *(float4*)(g_ksumpart + (bh * SPLITS + split) * DD + tid * 4) = s;
    }
}

// ---------------- K6: reduce partials -> ksum + KVT bf16 hi/lo ----------------
// grid BH, block 256, dyn smem 132608
__global__ void __launch_bounds__(256) k6_reduce() {
    extern __shared__ __align__(16) unsigned char smb[];
    float* acc = (float*)smb;                            // [128][129]
    unsigned* oh = (unsigned*)(smb + 128*129*4);         // [128][65]
    unsigned* ol = (unsigned*)(smb + 128*129*4 + 128*65*4);

    int bh = blockIdx.x, tid = threadIdx.x;
    for (int idx = tid; idx < DD * DD; idx += 256) {
        float s = 0.f;
#pragma unroll
        for (int sp = 0; sp < SPLITS; sp++)
            s += g_kvpart[(size_t)(bh * SPLITS + sp) * DD * DD + idx];
        acc[(idx >> 7) * 129 + (idx & 127)] = s;
    }
    if (tid < DD) {
        float s = 0.f;
#pragma unroll
        for (int sp = 0; sp < SPLITS; sp++) s += g_ksumpart[(bh * SPLITS + sp) * DD + tid];
        g_ksum[bh * DD + tid] = s;
    }
    __syncthreads();
    int e = tid >> 1, half = tid & 1;
#pragma unroll 4
    for (int i = 0; i < 32; i++) {
        int d = half * 64 + 2 * i;
        float x0 = acc[d * 129 + e], x1 = acc[(d + 1) * 129 + e];
        unsigned short h0, q0, h1, q1;
        cvt_hilo(x0, h0, q0); cvt_hilo(x1, h1, q1);
        oh[e * 65 + half * 32 + i] = (unsigned)h0 | ((unsigned)h1 << 16);
        ol[e * 65 + half * 32 + i] = (unsigned)q0 | ((unsigned)q1 << 16);
    }
    __syncthreads();
    for (int idx = tid; idx < 8192; idx += 256) {
        int r = idx >> 6, c = idx & 63;
        size_t di = (size_t)(bh * DD + r) * (DD/2) + c;
        g_kvT_hi[di] = oh[r * 65 + c];
        g_kvT_lo[di] = ol[r * 65 + c];
    }
}

// ---------------- K7: HMMA GEMM out = phiQ @ KV / den ----------------
// grid (LL/128, BH), block 256, dyn smem 65536
__global__ void __launch_bounds__(256, 2) k7_gemm(const float* __restrict__ phiQ,
                                                  float* __restrict__ out) {
    extern __shared__ __align__(16) unsigned char smb[];
    unsigned sbase = smem_u32(smb);
    __shared__ float sden[DD];
    __shared__ float ksp[DD];
    const int ALO = 16384, BHI = 32768, BLO = 49152;

    int chunk = blockIdx.x, bh = blockIdx.y, tid = threadIdx.x;
    int wid = tid >> 5, lane = tid & 31;
    int warpM = (wid >> 1) * 32, warpN = (wid & 1) * 64;
    size_t base = head_base(bh);
    int l0 = chunk * 128;

    if (tid < DD) ksp[tid] = g_ksum[bh * DD + tid];
    __syncthreads();

    float acc[2][8][4];
#pragma unroll
    for (int mt = 0; mt < 2; mt++)
#pragma unroll
        for (int nt = 0; nt < 8; nt++)
#pragma unroll
            for (int c = 0; c < 4; c++) acc[mt][nt][c] = 0.f;
    float denAcc[8];
#pragma unroll
    for (int i = 0; i < 8; i++) denAcc[i] = 0.f;

    for (int ch = 0; ch < 2; ch++) {
        for (int idx = tid; idx < 1024; idx += 256) {
            int row = idx >> 3, c8 = idx & 7;
            size_t src = (size_t)(bh * DD + row) * (DD/2) + ch * 32 + c8 * 4;
            unsigned off = sw(row * 128 + c8 * 16);
            *(uint4*)(smb + BHI + off) = *(const uint4*)(g_kvT_hi + src);
            *(uint4*)(smb + BLO + off) = *(const uint4*)(g_kvT_lo + src);
        }
#pragma unroll
        for (int it = 0; it < 8; it++) {
            int idx = tid + it * 256;
            int row = idx >> 4, c4 = idx & 15;
            int dg = ch * 64 + c4 * 4;
            float4 v = *(const float4*)(phiQ + base + (size_t)(l0 + row) * STRIDE_L + dg);
            float p = v.x * ksp[dg] + v.y * ksp[dg+1] + v.z * ksp[dg+2] + v.w * ksp[dg+3];
#pragma unroll
            for (int o = 8; o; o >>= 1) p += __shfl_xor_sync(0xffffffffu, p, o);
            denAcc[it] += p;
            unsigned short h0, q0, h1, q1, h2, q2, h3, q3;
            cvt_hilo(v.x, h0, q0); cvt_hilo(v.y, h1, q1);
            cvt_hilo(v.z, h2, q2); cvt_hilo(v.w, h3, q3);
            unsigned off = sw((unsigned)(row * 128 + c4 * 8));
            *(uint2*)(smb + off)       = make_uint2((unsigned)h0 | ((unsigned)h1 << 16),
                                                    (unsigned)h2 | ((unsigned)h3 << 16));
            *(uint2*)(smb + ALO + off) = make_uint2((unsigned)q0 | ((unsigned)q1 << 16),
                                                    (unsigned)q2 | ((unsigned)q3 << 16));
        }
        __syncthreads();
#pragma unroll
        for (int kk = 0; kk < 4; kk++) {
            unsigned ah[2][4], al[2][4];
#pragma unroll
            for (int mt = 0; mt < 2; mt++) {
                unsigned aoff = sw((warpM + mt * 16 + (lane & 15)) * 128 + kk * 32 + (lane >> 4) * 16);
                ldsm4(ah[mt], sbase + aoff);
                ldsm4(al[mt], sbase + ALO + aoff);
            }
#pragma unroll
            for (int np = 0; np < 4; np++) {
                unsigned bhr[4], blr[4];
                unsigned boff = sw((warpN + (np * 2 + (lane >> 4)) * 8 + (lane & 7)) * 128
                                   + kk * 32 + ((lane >> 3) & 1) * 16);
                ldsm4(bhr, sbase + BHI + boff);
                ldsm4(blr, sbase + BLO + boff);
#pragma unroll
                for (int mt = 0; mt < 2; mt++) {
                    mma16816(acc[mt][np*2],   ah[mt], bhr[0], bhr[1]);
                    mma16816(acc[mt][np*2],   al[mt], bhr[0], bhr[1]);
                    mma16816(acc[mt][np*2],   ah[mt], blr[0], blr[1]);
                    mma16816(acc[mt][np*2+1], ah[mt], bhr[2], bhr[3]);
                    mma16816(acc[mt][np*2+1], al[mt], bhr[2], bhr[3]);
                    mma16816(acc[mt][np*2+1], ah[mt], blr[2], blr[3]);
                }
            }
        }
        __syncthreads();
    }
    if ((tid & 15) == 0) {
#pragma unroll
        for (int it = 0; it < 8; it++) sden[(tid >> 4) + it * 16] = denAcc[it] + EPS;
    }
    __syncthreads();

    int g = lane >> 2, qc = (lane & 3) * 2;
#pragma unroll
    for (int mt = 0; mt < 2; mt++) {
        int row = warpM + mt * 16 + g;
        float d0 = 1.0f / sden[row], d1 = 1.0f / sden[row + 8];
#pragma unroll
        for (int nt = 0; nt < 8; nt++) {
            int col = warpN + nt * 8 + qc;
            float* p0 = out + base + (size_t)(l0 + row) * STRIDE_L + col;
            float* p1 = out + base + (size_t)(l0 + row + 8) * STRIDE_L + col;
            *(float2*)p0 = make_float2(acc[mt][nt][0] * d0, acc[mt][nt][1] * d0);
            *(float2*)p1 = make_float2(acc[mt][nt][2] * d1, acc[mt][nt][3] * d1);
        }
    }
}

// ---------------- launch ----------------
extern "C" void kernel_launch(void* const* d_in, const int* in_sizes, int n_in,
                              void* d_out, int out_size) {
    const float* Q    = (const float*)d_in[0];
    const float* K    = (const float*)d_in[1];
    const float* V    = (const float*)d_in[2];
    const float* phiQ = (const float*)d_in[3];
    const float* phiK = (const float*)d_in[4];
    float* out = (float*)d_out;

    static bool attr_set = false;
    if (!attr_set) {
        cudaFuncSetAttribute(k5_gemm,   cudaFuncAttributeMaxDynamicSharedMemorySize, 69632);
        cudaFuncSetAttribute(k6_reduce, cudaFuncAttributeMaxDynamicSharedMemorySize, 132608);
        cudaFuncSetAttribute(k7_gemm,   cudaFuncAttributeMaxDynamicSharedMemorySize, 65536);
        attr_set = true;
    }

    k_qsum<<<dim3(SPLITS, BH), 128>>>(Q);
    k_qred<<<BH, 128>>>();
    k_scores<<<dim3(BH, LL / 8), 256>>>(K);
    k_softmax<<<BH, 256>>>();
    k5_gemm<<<dim3(SPLITS, BH), 256, 69632>>>(phiK, V);
    k6_reduce<<<BH, 256, 132608>>>();
    k7_gemm<<<dim3(LL/128, BH), 256, 65536>>>(phiQ, out);
}